// round 13
// baseline (speedup 1.0000x reference)
#include <cuda_runtime.h>
#include <cuda_bf16.h>
#include <math.h>
#include <cstdint>

// NeRFRenderer null-scattering marcher (max_depths=1): all tot replicas of a
// ray are identical -> single per-ray eval: ray-sphere hit, equirect env-map
// bilinear sample, attenuate.
//
// inputs: d_in[0] rays_o f32[N,3], d_in[1] rays_d f32[N,3],
//         d_in[2] env_map f32[1,3,16,32], d_in[3..4] step counts (cancel).
// output: f32 [N,3]
//
// R12: single wave + warp-independent pipelines. 128 CTAs x 128 threads
// (one CTA wave over 148 SMs, minimal dispatch), and each of the 4 warps
// stages the 6KB env map into its OWN smem slice (12 float4/lane) so the
// only sync is __syncwarp — no cross-warp barrier skew, T_CTA = slowest
// independent warp. Combines R6's single-wave geometry with R11's
// barrier-free warp pipeline.

#define ENV_H 16
#define ENV_W 32
#define ENV_HW (ENV_H * ENV_W)
#define ENV_ELEMS (3 * ENV_HW)              // 1536 floats = 384 float4
#define SIGMA_MAJORANT 0.1f
#define PI_F 3.14159265358979323846f
#define THREADS 128
#define WARPS (THREADS / 32)
#define F4_PER_LANE (ENV_ELEMS / 4 / 32)    // 12

// fast acos, max err ~6.7e-5 rad
__device__ __forceinline__ float acos_fast(float x) {
    float ax = fabsf(x);
    float r = sqrtf(1.0f - ax) *
              (1.5707288f + ax * (-0.2121144f + ax * (0.0742610f + ax * (-0.0187293f))));
    return x < 0.0f ? (PI_F - r) : r;
}

// atan on [0,1], max err ~1e-5 rad
__device__ __forceinline__ float atan_poly(float a) {
    float s = a * a;
    return a * (0.9998660f + s * (-0.3302995f + s * (0.1801410f +
               s * (-0.0851330f + s * 0.0208351f))));
}

// fast atan2 (returns 0 at (0,0), matching nan_to_num in the reference)
__device__ __forceinline__ float atan2_fast(float y, float x) {
    float ay = fabsf(y), ax = fabsf(x);
    bool swap = ay > ax;
    float num = swap ? ax : ay;
    float den = swap ? ay : ax;
    den = fmaxf(den, 1e-30f);
    float r = atan_poly(__fdividef(num, den));
    if (swap) r = 1.57079632679f - r;
    if (x < 0.0f) r = PI_F - r;
    return y < 0.0f ? -r : r;
}

__global__ void __launch_bounds__(THREADS)
nerf_env_kernel(const float* __restrict__ rays_o,
                const float* __restrict__ rays_d,
                const float* __restrict__ env,
                float* __restrict__ out,
                int N)
{
    // one private 6KB env copy per warp -> no cross-warp barrier needed
    __shared__ float s_env_all[WARPS * ENV_ELEMS];

    const int t    = threadIdx.x;
    const int warp = t >> 5;
    const int lane = t & 31;
    float* s_env = s_env_all + warp * ENV_ELEMS;

    const int i = blockIdx.x * THREADS + t;
    const bool active = (i < N);
    const int ii = active ? i : 0;

    // issue env preload first: 384 float4 per warp, 12 per lane
    const float4* __restrict__ env4 = (const float4*)env;
    float4 e[F4_PER_LANE];
#pragma unroll
    for (int k = 0; k < F4_PER_LANE; k++)
        e[k] = env4[lane + k * 32];

    // ray loads
    const float ox = rays_o[3 * ii + 0];
    const float oy = rays_o[3 * ii + 1];
    const float oz = rays_o[3 * ii + 2];
    const float dx = rays_d[3 * ii + 0];
    const float dy = rays_d[3 * ii + 1];
    const float dz = rays_d[3 * ii + 2];

    // ---- env-independent math (overlaps the load latency above) ----
    const float a = dx * dx + dy * dy + dz * dz;
    const float c = ox * ox + oy * oy + oz * oz - 1.0f;
    const float b = 2.0f * (ox * dx + oy * dy + oz * dz);
    const float delta = b * b - 4.0f * a * c;
    const float sq = sqrtf(delta > 0.0f ? delta : 1.0f);
    const float t_hit = __fdividef(-b + sq, 2.0f * a);
    const bool valid = (delta > 0.0f) && (t_hit >= 0.0f);

    const float hx = ox + dx * t_hit;
    const float hy = oy + dy * t_hit;
    const float hz = oz + dz * t_hit;

    // grid-sample coords, affine folded in:
    //   iy = (H/2)*(atan2/pi) + (H-1)/2 ;  ix = (W/pi)*acos(yc) - 0.5
    const float iy = atan2_fast(hx, -hz) * ((float)ENV_H * 0.5f / PI_F)
                   + ((float)ENV_H - 1.0f) * 0.5f;
    const float yc = fminf(fmaxf(hy, -1.0f + 1e-6f), 1.0f - 1e-6f);
    const float ix = acos_fast(yc) * ((float)ENV_W / PI_F) - 0.5f;

    const float fx0 = floorf(ix);
    const float fy0 = floorf(iy);
    const float wx1 = ix - fx0;
    const float wy1 = iy - fy0;
    const int x0 = (int)fx0;
    const int y0 = (int)fy0;

    const int   xs[2]  = {x0, x0 + 1};
    const int   ys[2]  = {y0, y0 + 1};
    const float wxs[2] = {1.0f - wx1, wx1};
    const float wys[2] = {1.0f - wy1, wy1};

    // ---- commit env to this warp's smem slice (in-warp only), gather ----
    float4* s_env4 = (float4*)s_env;
#pragma unroll
    for (int k = 0; k < F4_PER_LANE; k++)
        s_env4[lane + k * 32] = e[k];
    __syncwarp();

    float acc0 = 0.0f, acc1 = 0.0f, acc2 = 0.0f;
#pragma unroll
    for (int jy = 0; jy < 2; jy++) {
#pragma unroll
        for (int jx = 0; jx < 2; jx++) {
            const int xcc = xs[jx];
            const int ycc = ys[jy];
            const bool inb = (xcc >= 0) && (xcc <= ENV_W - 1) &&
                             (ycc >= 0) && (ycc <= ENV_H - 1);
            const float w = wxs[jx] * wys[jy] * (inb ? 1.0f : 0.0f);
            const int xi = min(max(xcc, 0), ENV_W - 1);
            const int yi = min(max(ycc, 0), ENV_H - 1);
            const int base = yi * ENV_W + xi;
            acc0 = fmaf(w, s_env[base],               acc0);
            acc1 = fmaf(w, s_env[ENV_HW + base],      acc1);
            acc2 = fmaf(w, s_env[2 * ENV_HW + base],  acc2);
        }
    }

    if (active) {
        const float st = SIGMA_MAJORANT * t_hit;
        out[3 * i + 0] = valid ? __expf(acc0 - st) : 0.0f;
        out[3 * i + 1] = valid ? __expf(acc1 - st) : 0.0f;
        out[3 * i + 2] = valid ? __expf(acc2 - st) : 0.0f;
    }
}

extern "C" void kernel_launch(void* const* d_in, const int* in_sizes, int n_in,
                              void* d_out, int out_size)
{
    const float* rays_o = (const float*)d_in[0];
    const float* rays_d = (const float*)d_in[1];
    const float* env    = (const float*)d_in[2];
    float* out = (float*)d_out;

    const int N = in_sizes[0] / 3;
    const int blocks = (N + THREADS - 1) / THREADS;
    nerf_env_kernel<<<blocks, THREADS>>>(rays_o, rays_d, env, out, N);
}